// round 13
// baseline (speedup 1.0000x reference)
#include <cuda_runtime.h>
#include <cuda_bf16.h>

// NonLocalMeans: x [N,3,512,512] f32 -> out [N,3,512,512] f32
//   y = luminance(clip(x)); per shift s in [-5,5]^2:
//     D(p,s) = sum_{t in [-2,2]^2} (y(p+t) - y(p+t-s))^2   (circular)
//     w = exp(-sqrt(D)/3);  out(p) = clip( sum_s w * x(p-s) / sum_s w )

#define IMG_H 512
#define IMG_W 512
#define WMASK 511
#define TSZ   32          // tile = 32x32 output pixels per CTA
#define YDIM  46          // tile + 2*(5+2) halo
#define YSTR  47          // odd stride -> conflict-free
#define VSTR  37          // sv stride (32 rows x 36 cols)
#define XDIM  42          // tile + 2*5 halo
#define XSTR  43

__global__ __launch_bounds__(256)
void nlm_kernel(const float* __restrict__ x, float* __restrict__ out)
{
    __shared__ float sy [YDIM * YSTR];   // luminance tile, halo 7
    __shared__ float sv [TSZ  * VSTR];   // per-shift vertical 5-sums (32 x 36)
    __shared__ float sxr[XDIM * XSTR];   // x channel tiles, halo 5
    __shared__ float sxg[XDIM * XSTR];
    __shared__ float sxb[XDIM * XSTR];

    const int tid = threadIdx.x;
    const int gx0 = blockIdx.x * TSZ;
    const int gy0 = blockIdx.y * TSZ;
    const int n   = blockIdx.z;

    const float* xr = x + (size_t)n * 3 * IMG_H * IMG_W;
    const float* xg = xr + IMG_H * IMG_W;
    const float* xb = xg + IMG_H * IMG_W;

    // ---- load luminance tile (halo 7), circular wrap via &511 ----
    for (int idx = tid; idx < YDIM * YDIM; idx += 256) {
        int i = idx / YDIM, j = idx - i * YDIM;
        int gy = (gy0 + i - 7) & WMASK;
        int gx = (gx0 + j - 7) & WMASK;
        int g  = gy * IMG_W + gx;
        float r  = __saturatef(xr[g]);
        float gg = __saturatef(xg[g]);
        float b  = __saturatef(xb[g]);
        sy[i * YSTR + j] = 0.299f * r + 0.587f * gg + 0.114f * b;
    }
    // ---- load x tiles (halo 5) ----
    for (int idx = tid; idx < XDIM * XDIM; idx += 256) {
        int i = idx / XDIM, j = idx - i * XDIM;
        int gy = (gy0 + i - 5) & WMASK;
        int gx = (gx0 + j - 5) & WMASK;
        int g  = gy * IMG_W + gx;
        sxr[i * XSTR + j] = xr[g];
        sxg[i * XSTR + j] = xg[g];
        sxb[i * XSTR + j] = xb[g];
    }
    __syncthreads();

    // ---- phase-1 task assignment: 144 threads = 36 cols x 4 row-segments(8) ----
    // sd-logical entry (i_sd, j_sd) <-> diff2 at global (gy0+i_sd-2, gx0+j_sd-2)
    // unshifted Y at that point: sy[(i_sd+5)*YSTR + (j_sd+5)]  -- shift-invariant,
    // hoisted into registers once.
    const int  p1s   = tid / 36;             // segment (rows 8s..8s+11 of sd)
    const int  p1j   = tid - p1s * 36;       // sd column
    const bool p1act = tid < 144;
    const int  ybase = (8 * p1s + 5) * YSTR + (p1j + 5);
    const int  svbase = (8 * p1s) * VSTR + p1j;
    float yreg[12];
    if (p1act) {
        #pragma unroll
        for (int k = 0; k < 12; ++k) yreg[k] = sy[ybase + k * YSTR];
    }

    // ---- phase-2 task: thread owns 4 horizontally adjacent output pixels ----
    const int prow  = tid >> 3;              // output row within tile (0..31)
    const int pg    = tid & 7;               // column group (cols 4g..4g+3)
    const int eoff  = prow * VSTR + 4 * pg;  // sv base for horizontal window
    const int abase = (prow + 5) * XSTR + (4 * pg + 5);

    float wacc[4] = {0,0,0,0};
    float accr[4] = {0,0,0,0};
    float accg[4] = {0,0,0,0};
    float accb[4] = {0,0,0,0};

    #pragma unroll 1
    for (int sxs = -5; sxs <= 5; ++sxs) {
        #pragma unroll 1
        for (int sys = -5; sys <= 5; ++sys) {
            // phase 1: vertical 5-sums of squared diffs, sliding in registers
            if (p1act) {
                int off = ybase - sys * YSTR - sxs;   // Y(q - s)
                float d[12];
                #pragma unroll
                for (int k = 0; k < 12; ++k) {
                    float t = yreg[k] - sy[off + k * YSTR];
                    d[k] = t * t;
                }
                float v = d[0] + d[1] + d[2] + d[3] + d[4];
                sv[svbase] = v;
                #pragma unroll
                for (int k = 1; k < 8; ++k) {
                    v += d[k + 4] - d[k - 1];
                    sv[svbase + k * VSTR] = v;
                }
            }
            __syncthreads();

            // phase 2: horizontal 5-sum (sliding), weight, accumulate
            {
                float v[8];
                #pragma unroll
                for (int k = 0; k < 8; ++k) v[k] = sv[eoff + k];
                float D = v[0] + v[1] + v[2] + v[3] + v[4];
                int aoff = abase - sys * XSTR - sxs;  // x(p - s)
                #pragma unroll
                for (int k = 0; k < 4; ++k) {
                    // clamp: sliding sums can underflow to -eps; exp(+big)=inf otherwise
                    float Dk = fmaxf(D, 0.0f);
                    float sq = Dk * rsqrtf(fmaxf(Dk, 1e-20f));  // sqrt(D), 0-safe
                    float w  = __expf(sq * (-1.0f / 3.0f));
                    wacc[k] += w;
                    accr[k]  = fmaf(w, sxr[aoff + k], accr[k]);
                    accg[k]  = fmaf(w, sxg[aoff + k], accg[k]);
                    accb[k]  = fmaf(w, sxb[aoff + k], accb[k]);
                    if (k < 3) D += v[k + 5] - v[k];
                }
            }
            __syncthreads();   // protect sv before next shift overwrites it
        }
    }

    // ---- write output ----
    float* outr = out + (size_t)n * 3 * IMG_H * IMG_W;
    int gbase = (gy0 + prow) * IMG_W + gx0 + 4 * pg;
    #pragma unroll
    for (int k = 0; k < 4; ++k) {
        float inv = __fdividef(1.0f, wacc[k]);   // wacc >= 1 (center weight = 1)
        outr[gbase + k]                         = __saturatef(accr[k] * inv);
        outr[gbase + k + IMG_H * IMG_W]         = __saturatef(accg[k] * inv);
        outr[gbase + k + 2 * IMG_H * IMG_W]     = __saturatef(accb[k] * inv);
    }
}

extern "C" void kernel_launch(void* const* d_in, const int* in_sizes, int n_in,
                              void* d_out, int out_size)
{
    const float* x = (const float*)d_in[0];
    float* out = (float*)d_out;
    int nbatch = in_sizes[0] / (3 * IMG_H * IMG_W);   // expect 2
    dim3 grid(IMG_W / TSZ, IMG_H / TSZ, nbatch);
    nlm_kernel<<<grid, 256>>>(x, out);
}

// round 14
// speedup vs baseline: 1.1216x; 1.1216x over previous
#include <cuda_runtime.h>
#include <cuda_bf16.h>

// NonLocalMeans: x [N,3,512,512] f32 -> out [N,3,512,512] f32
//   y = luminance(clip(x)); per shift s in [-5,5]^2:
//     D(p,s) = sum_{t in [-2,2]^2} (y(p+t) - y(p+t-s))^2   (circular)
//     w = exp(-sqrt(D)/3);  out(p) = clip( sum_s w * x(p-s) / sum_s w )

#define IMG_H 512
#define IMG_W 512
#define WMASK 511
#define TSZ   32          // tile = 32x32 output pixels per CTA
#define YDIM  46          // tile + 2*(5+2) halo
#define YSTR  47          // odd stride -> conflict-free scalar column access
#define VSTR  40          // sv stride (32 rows x 36 cols used), mult of 4 for float4
#define SVSZ  (TSZ * VSTR)
#define XDIM  42          // tile + 2*5 halo
#define XSTR  44          // mult of 4 for float4 row loads

__device__ __forceinline__ void do_p1(const float* __restrict__ sy,
                                      float* __restrict__ svb,
                                      const float yreg[12],
                                      int ybase, int svbase,
                                      int sys, int sxs, bool act)
{
    if (act) {
        int off = ybase - sys * YSTR - sxs;   // Y(q - s)
        float d[12];
        #pragma unroll
        for (int k = 0; k < 12; ++k) {
            float t = yreg[k] - sy[off + k * YSTR];
            d[k] = t * t;
        }
        float v = d[0] + d[1] + d[2] + d[3] + d[4];
        svb[svbase] = v;
        #pragma unroll
        for (int k = 1; k < 8; ++k) {
            v += d[k + 4] - d[k - 1];
            svb[svbase + k * VSTR] = v;
        }
    }
}

__global__ __launch_bounds__(256, 2)
void nlm_kernel(const float* __restrict__ x, float* __restrict__ out)
{
    __shared__ __align__(16) float sy [YDIM * YSTR];   // luminance, halo 7
    __shared__ __align__(16) float sv [2 * SVSZ];      // double-buffered vertical sums
    __shared__ __align__(16) float sxr[XDIM * XSTR];   // x channels, halo 5
    __shared__ __align__(16) float sxg[XDIM * XSTR];
    __shared__ __align__(16) float sxb[XDIM * XSTR];

    const int tid = threadIdx.x;
    const int gx0 = blockIdx.x * TSZ;
    const int gy0 = blockIdx.y * TSZ;
    const int n   = blockIdx.z;

    const float* xr = x + (size_t)n * 3 * IMG_H * IMG_W;
    const float* xg = xr + IMG_H * IMG_W;
    const float* xb = xg + IMG_H * IMG_W;

    // ---- load luminance tile (halo 7), circular wrap via &511 ----
    for (int idx = tid; idx < YDIM * YDIM; idx += 256) {
        int i = idx / YDIM, j = idx - i * YDIM;
        int gy = (gy0 + i - 7) & WMASK;
        int gx = (gx0 + j - 7) & WMASK;
        int g  = gy * IMG_W + gx;
        float r  = __saturatef(xr[g]);
        float gg = __saturatef(xg[g]);
        float b  = __saturatef(xb[g]);
        sy[i * YSTR + j] = 0.299f * r + 0.587f * gg + 0.114f * b;
    }
    // ---- load x tiles (halo 5) ----
    for (int idx = tid; idx < XDIM * XDIM; idx += 256) {
        int i = idx / XDIM, j = idx - i * XDIM;
        int gy = (gy0 + i - 5) & WMASK;
        int gx = (gx0 + j - 5) & WMASK;
        int g  = gy * IMG_W + gx;
        sxr[i * XSTR + j] = xr[g];
        sxg[i * XSTR + j] = xg[g];
        sxb[i * XSTR + j] = xb[g];
    }
    __syncthreads();

    // ---- phase-1 assignment: 144 threads = 36 cols x 4 row-segments(8) ----
    const int  p1s    = tid / 36;
    const int  p1j    = tid - p1s * 36;
    const bool p1act  = tid < 144;
    const int  ybase  = (8 * p1s + 5) * YSTR + (p1j + 5);
    const int  svbase = (8 * p1s) * VSTR + p1j;
    float yreg[12];
    if (p1act) {
        #pragma unroll
        for (int k = 0; k < 12; ++k) yreg[k] = sy[ybase + k * YSTR];
    }

    // ---- phase-2: thread owns 4 horizontally adjacent output pixels ----
    const int prow = tid >> 3;              // output row (0..31)
    const int pg   = tid & 7;               // column group (cols 4g..4g+3)
    const int eoff = prow * VSTR + 4 * pg;  // sv base for horizontal window

    float wacc[4] = {0,0,0,0};
    float accr[4] = {0,0,0,0};
    float accg[4] = {0,0,0,0};
    float accb[4] = {0,0,0,0};

    // prologue: P1 for first shift (sys=-5, sxs=-5) into buffer 0
    do_p1(sy, sv, yreg, ybase, svbase, -5, -5, p1act);
    __syncthreads();

    int buf = 0;
    #pragma unroll 1
    for (int sys = -5; sys <= 5; ++sys) {
        // cache this sys's x row segments in registers (cols [4pg, 4pg+13])
        float xr_[16], xg_[16], xb_[16];
        {
            int rb = (prow + 5 - sys) * XSTR + 4 * pg;
            #pragma unroll
            for (int m = 0; m < 4; ++m) {
                float4 tr = *(const float4*)&sxr[rb + 4 * m];
                float4 tg = *(const float4*)&sxg[rb + 4 * m];
                float4 tb = *(const float4*)&sxb[rb + 4 * m];
                xr_[4*m] = tr.x; xr_[4*m+1] = tr.y; xr_[4*m+2] = tr.z; xr_[4*m+3] = tr.w;
                xg_[4*m] = tg.x; xg_[4*m+1] = tg.y; xg_[4*m+2] = tg.z; xg_[4*m+3] = tg.w;
                xb_[4*m] = tb.x; xb_[4*m+1] = tb.y; xb_[4*m+2] = tb.z; xb_[4*m+3] = tb.w;
            }
        }

        #pragma unroll
        for (int sxs = -5; sxs <= 5; ++sxs) {
            // pipelined P1 for the NEXT shift into the other buffer
            {
                int nsxs = sxs + 1, nsys = sys;
                if (nsxs > 5) { nsxs = -5; ++nsys; }
                if (nsys <= 5)
                    do_p1(sy, sv + (buf ^ 1) * SVSZ, yreg, ybase, svbase,
                          nsys, nsxs, p1act);
            }

            // phase 2 on current buffer
            {
                const float* svb = sv + buf * SVSZ;
                float v[8];
                float4 a = *(const float4*)&svb[eoff];
                float4 b = *(const float4*)&svb[eoff + 4];
                v[0]=a.x; v[1]=a.y; v[2]=a.z; v[3]=a.w;
                v[4]=b.x; v[5]=b.y; v[6]=b.z; v[7]=b.w;
                float D = v[0] + v[1] + v[2] + v[3] + v[4];
                #pragma unroll
                for (int k = 0; k < 4; ++k) {
                    float Dk = fmaxf(D, 0.0f);       // sliding sums can go -eps
                    float sq;
                    asm("sqrt.approx.f32 %0, %1;" : "=f"(sq) : "f"(Dk));
                    float w = __expf(sq * (-1.0f / 3.0f));
                    int li = 5 - sxs + k;            // compile-time: 0..13
                    wacc[k] += w;
                    accr[k]  = fmaf(w, xr_[li], accr[k]);
                    accg[k]  = fmaf(w, xg_[li], accg[k]);
                    accb[k]  = fmaf(w, xb_[li], accb[k]);
                    if (k < 3) D += v[k + 5] - v[k];
                }
            }

            buf ^= 1;
            __syncthreads();
        }
    }

    // ---- write output ----
    float* outr = out + (size_t)n * 3 * IMG_H * IMG_W;
    int gbase = (gy0 + prow) * IMG_W + gx0 + 4 * pg;
    #pragma unroll
    for (int k = 0; k < 4; ++k) {
        float inv = __fdividef(1.0f, wacc[k]);   // wacc >= 1 (center weight = 1)
        outr[gbase + k]                     = __saturatef(accr[k] * inv);
        outr[gbase + k + IMG_H * IMG_W]     = __saturatef(accg[k] * inv);
        outr[gbase + k + 2 * IMG_H * IMG_W] = __saturatef(accb[k] * inv);
    }
}

extern "C" void kernel_launch(void* const* d_in, const int* in_sizes, int n_in,
                              void* d_out, int out_size)
{
    const float* x = (const float*)d_in[0];
    float* out = (float*)d_out;
    int nbatch = in_sizes[0] / (3 * IMG_H * IMG_W);   // expect 2
    dim3 grid(IMG_W / TSZ, IMG_H / TSZ, nbatch);
    nlm_kernel<<<grid, 256>>>(x, out);
}

// round 15
// speedup vs baseline: 1.1300x; 1.0075x over previous
#include <cuda_runtime.h>
#include <cuda_bf16.h>

// NonLocalMeans: x [N,3,512,512] f32 -> out [N,3,512,512] f32
// Pipelined, 4-shift-batched producer/consumer inside one CTA.

#define IMG_H 512
#define IMG_W 512
#define WMASK 511
#define TSZ   32
#define YDIM  46
#define YSTR  47
#define VSTR  40
#define SVSZ  (TSZ * VSTR)     // 1280 floats per shift-slot
#define XDIM  42
#define XSTR  44

// dynamic shared memory layout (floats)
#define SY_OFF 0
#define SY_SZ  2164            // 46*47 = 2162, padded to mult of 4
#define SX_OFF (SY_OFF + SY_SZ)
#define SX_SZ  (XDIM * XSTR)   // 1848
#define SV_OFF (SX_OFF + 3 * SX_SZ)
#define SV_SZ  (8 * SVSZ)      // 2 buffers x 4 slots
#define SMEM_FLOATS (SV_OFF + SV_SZ)
#define SMEM_BYTES  (SMEM_FLOATS * 4)

// ---- phase 1: vertical 5-sums of squared luminance diffs for CNT shifts ----
template<int CNT>
__device__ __forceinline__ void p1_batch(const float* __restrict__ sy,
                                         float* __restrict__ svb,
                                         const float yreg[12],
                                         int ybase, int svbase,
                                         int nsys, int sxs0, bool act)
{
    if (!act) return;
    #pragma unroll
    for (int m = 0; m < CNT; ++m) {
        int off = ybase - nsys * YSTR - (sxs0 + m);   // Y(q - s)
        float d[12];
        #pragma unroll
        for (int kk = 0; kk < 12; ++kk) {
            float t = yreg[kk] - sy[off + kk * YSTR];
            d[kk] = t * t;
        }
        float v = d[0] + d[1] + d[2] + d[3] + d[4];
        float* s = svb + m * SVSZ + svbase;
        s[0] = v;
        #pragma unroll
        for (int kk = 1; kk < 8; ++kk) {
            v += d[kk + 4] - d[kk - 1];
            s[kk * VSTR] = v;
        }
    }
}

// ---- phase 2: horizontal 5-sum, weight, accumulate, for CNT shifts ----
// K = batch index within sys (sxs0 = -5 + 4K compile-time)
template<int K, int CNT>
__device__ __forceinline__ void p2_batch(const float* __restrict__ svb,
                                         int eoff,
                                         const float xr_[16], const float xg_[16],
                                         const float xb_[16],
                                         float wacc[4], float accr[4],
                                         float accg[4], float accb[4])
{
    #pragma unroll
    for (int m = 0; m < CNT; ++m) {
        const float* s = svb + m * SVSZ + eoff;
        float4 a = *(const float4*)(s);
        float4 b = *(const float4*)(s + 4);
        float v[8] = {a.x, a.y, a.z, a.w, b.x, b.y, b.z, b.w};
        float D = v[0] + v[1] + v[2] + v[3] + v[4];
        #pragma unroll
        for (int kk = 0; kk < 4; ++kk) {
            float Dk = fmaxf(D, 0.0f);                 // sliding sums can go -eps
            float sq;
            asm("sqrt.approx.f32 %0, %1;" : "=f"(sq) : "f"(Dk));
            float w;                                    // exp(-sq/3) = 2^(sq * -log2e/3)
            asm("ex2.approx.f32 %0, %1;" : "=f"(w) : "f"(sq * -0.48089834696f));
            const int li = 10 - 4 * K - m + kk;         // compile-time 0..13
            wacc[kk] += w;
            accr[kk] = fmaf(w, xr_[li], accr[kk]);
            accg[kk] = fmaf(w, xg_[li], accg[kk]);
            accb[kk] = fmaf(w, xb_[li], accb[kk]);
            if (kk < 3) D += v[kk + 5] - v[kk];
        }
    }
}

__global__ __launch_bounds__(256, 2)
void nlm_kernel(const float* __restrict__ x, float* __restrict__ out)
{
    extern __shared__ __align__(16) float smem[];
    float* sy  = smem + SY_OFF;
    float* sxr = smem + SX_OFF;
    float* sxg = sxr + SX_SZ;
    float* sxb = sxg + SX_SZ;
    float* sv  = smem + SV_OFF;

    const int tid = threadIdx.x;
    const int gx0 = blockIdx.x * TSZ;
    const int gy0 = blockIdx.y * TSZ;
    const int n   = blockIdx.z;

    const float* xr = x + (size_t)n * 3 * IMG_H * IMG_W;
    const float* xg = xr + IMG_H * IMG_W;
    const float* xb = xg + IMG_H * IMG_W;

    // ---- load luminance tile (halo 7), circular wrap ----
    for (int idx = tid; idx < YDIM * YDIM; idx += 256) {
        int i = idx / YDIM, j = idx - i * YDIM;
        int g = ((gy0 + i - 7) & WMASK) * IMG_W + ((gx0 + j - 7) & WMASK);
        float r  = __saturatef(xr[g]);
        float gg = __saturatef(xg[g]);
        float b  = __saturatef(xb[g]);
        sy[i * YSTR + j] = 0.299f * r + 0.587f * gg + 0.114f * b;
    }
    // ---- load x tiles (halo 5) ----
    for (int idx = tid; idx < XDIM * XDIM; idx += 256) {
        int i = idx / XDIM, j = idx - i * XDIM;
        int g = ((gy0 + i - 5) & WMASK) * IMG_W + ((gx0 + j - 5) & WMASK);
        sxr[i * XSTR + j] = xr[g];
        sxg[i * XSTR + j] = xg[g];
        sxb[i * XSTR + j] = xb[g];
    }
    __syncthreads();

    // ---- phase-1 assignment: 144 threads = 36 cols x 4 row-segments ----
    const int  p1s    = tid / 36;
    const int  p1j    = tid - p1s * 36;
    const bool p1act  = tid < 144;
    const int  ybase  = (8 * p1s + 5) * YSTR + (p1j + 5);
    const int  svbase = (8 * p1s) * VSTR + p1j;
    float yreg[12];
    if (p1act) {
        #pragma unroll
        for (int kk = 0; kk < 12; ++kk) yreg[kk] = sy[ybase + kk * YSTR];
    }

    // ---- phase-2 assignment: thread owns 4 horizontally adjacent pixels ----
    const int prow = tid >> 3;
    const int pg   = tid & 7;
    const int eoff = prow * VSTR + 4 * pg;

    float wacc[4] = {0,0,0,0};
    float accr[4] = {0,0,0,0};
    float accg[4] = {0,0,0,0};
    float accb[4] = {0,0,0,0};
    float xr_[16], xg_[16], xb_[16];

    // prologue: P1 for batch (sys=-5, k=0) into buffer 0
    int par = 0;
    p1_batch<4>(sy, sv, yreg, ybase, svbase, -5, -5, p1act);
    __syncthreads();

#define KSTEP(K, CNT, NSYS, NSXS0, NCNT, HAVE_NEXT)                              \
    do {                                                                         \
        if (HAVE_NEXT)                                                           \
            p1_batch<NCNT>(sy, sv + (par ^ 1) * (4 * SVSZ), yreg, ybase,         \
                           svbase, (NSYS), (NSXS0), p1act);                      \
        p2_batch<K, CNT>(sv + par * (4 * SVSZ), eoff, xr_, xg_, xb_,             \
                         wacc, accr, accg, accb);                                \
        par ^= 1;                                                                \
        __syncthreads();                                                         \
    } while (0)

    #pragma unroll 1
    for (int sys_i = 0; sys_i < 11; ++sys_i) {
        const int sys = sys_i - 5;
        // cache this sys's x row segments in registers (cols [4pg-5 .. 4pg+8])
        {
            int rb = (prow + 5 - sys) * XSTR + 4 * pg;
            #pragma unroll
            for (int m = 0; m < 4; ++m) {
                float4 tr = *(const float4*)&sxr[rb + 4 * m];
                float4 tg = *(const float4*)&sxg[rb + 4 * m];
                float4 tb = *(const float4*)&sxb[rb + 4 * m];
                xr_[4*m]=tr.x; xr_[4*m+1]=tr.y; xr_[4*m+2]=tr.z; xr_[4*m+3]=tr.w;
                xg_[4*m]=tg.x; xg_[4*m+1]=tg.y; xg_[4*m+2]=tg.z; xg_[4*m+3]=tg.w;
                xb_[4*m]=tb.x; xb_[4*m+1]=tb.y; xb_[4*m+2]=tb.z; xb_[4*m+3]=tb.w;
            }
        }
        KSTEP(0, 4, sys,     -1, 4, true);          // consume sxs -5..-2, produce -1..2
        KSTEP(1, 4, sys,      3, 3, true);          // consume -1..2,     produce 3..5
        KSTEP(2, 3, sys + 1, -5, 4, sys_i < 10);    // consume 3..5,      produce next sys
    }
#undef KSTEP

    // ---- write output ----
    float* outr = out + (size_t)n * 3 * IMG_H * IMG_W;
    int gbase = (gy0 + prow) * IMG_W + gx0 + 4 * pg;
    #pragma unroll
    for (int kk = 0; kk < 4; ++kk) {
        float inv = __fdividef(1.0f, wacc[kk]);      // wacc >= 1 (center w = 1)
        outr[gbase + kk]                     = __saturatef(accr[kk] * inv);
        outr[gbase + kk + IMG_H * IMG_W]     = __saturatef(accg[kk] * inv);
        outr[gbase + kk + 2 * IMG_H * IMG_W] = __saturatef(accb[kk] * inv);
    }
}

extern "C" void kernel_launch(void* const* d_in, const int* in_sizes, int n_in,
                              void* d_out, int out_size)
{
    const float* x = (const float*)d_in[0];
    float* out = (float*)d_out;
    int nbatch = in_sizes[0] / (3 * IMG_H * IMG_W);   // expect 2
    cudaFuncSetAttribute(nlm_kernel,
                         cudaFuncAttributeMaxDynamicSharedMemorySize, SMEM_BYTES);
    dim3 grid(IMG_W / TSZ, IMG_H / TSZ, nbatch);
    nlm_kernel<<<grid, 256, SMEM_BYTES>>>(x, out);
}